// round 16
// baseline (speedup 1.0000x reference)
#include <cuda_runtime.h>
#include <math.h>

#define NB    32
#define HH    128
#define WW    128
#define CC    80
#define CHN   84
#define KTOP  100
#define CAP   2048
#define SORTN 2048
#define QCAP  1536
#define NITEM (HH * 16 * 20)       /* 40960 scratch items per batch */
#define GSPL  8                    /* gather blocks per batch */
#define GITEM (NITEM / GSPL)       /* 5120 items per gather block */

__device__ unsigned g_seg[NB][6][80];          /* zero-init = ord-map bottom */
__device__ float    g_scr[NB][HH][16][20];     /* max over 8x x 4ch cells   */
__device__ unsigned g_count[NB];
__device__ unsigned g_done[NB];
__device__ unsigned long long g_cand[NB][CAP];

__device__ __forceinline__ unsigned ordmap(float x) {
    unsigned u = __float_as_uint(x);
    return (u & 0x80000000u) ? ~u : (u | 0x80000000u);
}
__device__ __forceinline__ float ordunmap(unsigned u) {
    return __uint_as_float((u & 0x80000000u) ? (u ^ 0x80000000u) : ~u);
}
__device__ __forceinline__ void upd4(float4& a, float4 v) {
    a.x = fmaxf(a.x, v.x); a.y = fmaxf(a.y, v.y);
    a.z = fmaxf(a.z, v.z); a.w = fmaxf(a.w, v.w);
}

// ===== Kernel 1: segment maxima (certification inputs) + coarse max map =====
// Lean streaming body (R13-proven). Thread = (row, half, 4ch-group).
// Per half: seg m0={x0}, m1=[1..62], m2={x63}; also per-(8x,4ch) cell max.
__global__ void __launch_bounds__(320, 3) pre_kernel(const float* __restrict__ det) {
    __shared__ unsigned sm_max[6][80];

    const int t    = threadIdx.x;
    const int b    = blockIdx.y;
    const int row  = blockIdx.x * 8 + t / 40;       // 16 strips of 8 rows
    const int half = (t / 20) & 1;
    const int cgi  = t % 20;
    const int cg   = cgi * 4;

    for (int i = t; i < 480; i += 320) ((unsigned*)sm_max)[i] = 0u;
    __syncthreads();

    const float NEGINF = __int_as_float(0xff800000);
    const float* rp = det + ((size_t)(b * HH + row) * WW + half * 64) * CHN + cg;

    float4 m0, m2;
    float4 m1 = make_float4(NEGINF, NEGINF, NEGINF, NEGINF);
    #pragma unroll
    for (int g = 0; g < 8; g++) {
        float4 a = make_float4(NEGINF, NEGINF, NEGINF, NEGINF);
        #pragma unroll
        for (int xx = 0; xx < 8; xx++) {
            float4 v = *(const float4*)(rp + (g * 8 + xx) * CHN);
            upd4(a, v);
            if (g == 0 && xx == 0)      m0 = v;
            else if (g == 7 && xx == 7) m2 = v;
            else                        upd4(m1, v);
        }
        g_scr[b][row][half * 8 + g][cgi] =
            fmaxf(fmaxf(a.x, a.y), fmaxf(a.z, a.w));
    }

    const int sb = half * 3;
    atomicMax(&sm_max[sb + 0][cg + 0], ordmap(m0.x));
    atomicMax(&sm_max[sb + 0][cg + 1], ordmap(m0.y));
    atomicMax(&sm_max[sb + 0][cg + 2], ordmap(m0.z));
    atomicMax(&sm_max[sb + 0][cg + 3], ordmap(m0.w));
    atomicMax(&sm_max[sb + 1][cg + 0], ordmap(m1.x));
    atomicMax(&sm_max[sb + 1][cg + 1], ordmap(m1.y));
    atomicMax(&sm_max[sb + 1][cg + 2], ordmap(m1.z));
    atomicMax(&sm_max[sb + 1][cg + 3], ordmap(m1.w));
    atomicMax(&sm_max[sb + 2][cg + 0], ordmap(m2.x));
    atomicMax(&sm_max[sb + 2][cg + 1], ordmap(m2.y));
    atomicMax(&sm_max[sb + 2][cg + 2], ordmap(m2.z));
    atomicMax(&sm_max[sb + 2][cg + 3], ordmap(m2.w));
    __syncthreads();

    for (int i = t; i < 480; i += 320)
        atomicMax(&((unsigned*)g_seg[b])[i], ((unsigned*)sm_max)[i]);
}

// ===== Kernel 2: certify (redundant/block) + scan + gather + elected sort ===
__global__ void __launch_bounds__(256) gstopk_kernel(const float* __restrict__ det,
                                                     float* __restrict__ out) {
    const int b   = blockIdx.y;
    const int tid = threadIdx.x;
    const int lane = tid & 31, wid = tid >> 5;
    __shared__ unsigned long long sel[SORTN];    // 16KB (used by elected block)
    __shared__ unsigned fq[QCAP];                // 6KB fire queue
    __shared__ unsigned s_vals[256];
    __shared__ int s_nf, s_od;

    // ---- certification (identical in all 8 blocks of this batch) -----------
    // per (half, channel): interior max == region max => certified true peak
    unsigned val = 0u;
    if (tid < 160) {
        int h = tid / 80, ch = tid % 80;
        const unsigned* R = &g_seg[b][0][ch];
        unsigned R0 = R[0], R1 = R[80], R2 = R[160],
                 R3 = R[240], R4 = R[320], R5 = R[400];
        unsigned iu = h == 0 ? max(R1, R2) : max(R3, R4);
        unsigned ru = h == 0 ? max(iu, max(R0, R3)) : max(iu, max(R2, R5));
        if (iu == ru) val = iu;
    }
    s_vals[tid] = val;
    if (tid == 0) s_nf = 0;
    __syncthreads();
    for (unsigned k = 2; k <= 256; k <<= 1)
        for (unsigned j = k >> 1; j > 0; j >>= 1) {
            unsigned i = (unsigned)tid, ixj = i ^ j;
            if (ixj > i) {
                unsigned a = s_vals[i], q = s_vals[ixj];
                bool desc = ((i & k) == 0);
                if (desc ? (a < q) : (a > q)) { s_vals[i] = q; s_vals[ixj] = a; }
            }
            __syncthreads();
        }
    unsigned Tm = s_vals[99];
    float Tval, Tg;
    if (Tm == 0u) { Tval = -1e30f; Tg = -1e30f; }
    else {
        Tval = ordunmap(Tm);
        float sT = 1.0f / (1.0f + expf(-Tval));
        float a  = sT - 1e-4f;
        Tg = (a <= 0.0f) ? -1e30f : (logf(a / (1.0f - a)) - 1e-3f);
    }

    // ---- scan this block's 1/8 slice of the coarse max map -----------------
    const int i0 = blockIdx.x * GITEM;
    const float* scr = &g_scr[b][0][0][0];
    for (int i = tid; i < GITEM; i += 256) {
        if (scr[i0 + i] >= Tg) {
            int p = atomicAdd(&s_nf, 1);
            if (p < QCAP) fq[p] = (unsigned)(i0 + i);
        }
    }
    __syncthreads();
    const int nf = s_nf;
    const bool fallback = (nf > QCAP);           // degenerate inputs only
    const int total = fallback ? GITEM : nf;
    const float* base = det + (size_t)b * HH * WW * CHN;

    // ---- gather: one warp per fired item, one lane per cell (8x x 4ch) -----
    for (int f = wid; f < total; f += 8) {
        unsigned item = fallback ? (unsigned)(i0 + f) : fq[f];
        int cgi = (int)(item % 20u);
        int rx  = (int)(item / 20u);
        int xg  = rx % 16, r = rx / 16;
        int x   = xg * 8 + (lane >> 2);
        int ch  = cgi * 4 + (lane & 3);

        float ctr = base[((size_t)r * WW + x) * CHN + ch];
        float mm = ctr;
        bool cand = false;
        if (ctr >= Tg) {
            #pragma unroll
            for (int dy = -1; dy <= 1; dy++) {
                int ry = min(HH - 1, max(0, r + dy));
                #pragma unroll
                for (int dx = -1; dx <= 1; dx++) {
                    int rxx = min(WW - 1, max(0, x + dx));
                    mm = fmaxf(mm, base[((size_t)ry * WW + rxx) * CHN + ch]);
                }
            }
            float d = mm - ctr;
            if (mm >= Tval) {
                if (d < 3.6e-4f) cand = true;        // sig-diff <= d/4 < 1e-4
                else if (d < 0.0421f ||
                         fmaxf(fabsf(ctr), fabsf(mm)) >= 6.0f) {
                    float s  = 1.0f / (1.0f + expf(-ctr));
                    float sm = 1.0f / (1.0f + expf(-mm));
                    cand = fabsf(s - sm) < 1e-4f;
                }
            }
        }
        unsigned msk = __ballot_sync(0xFFFFFFFFu, cand);
        if (msk) {
            int leader = __ffs(msk) - 1;
            unsigned bp;
            if (lane == leader)
                bp = atomicAdd(&g_count[b], (unsigned)__popc(msk));
            bp = __shfl_sync(0xFFFFFFFFu, bp, leader);
            if (cand) {
                float sg = 1.0f / (1.0f + expf(-mm));
                unsigned idx = ((unsigned)r * WW + (unsigned)x) * CC + (unsigned)ch;
                unsigned pos = bp + __popc(msk & ((1u << lane) - 1u));
                if (pos < CAP)
                    g_cand[b][pos] = ((unsigned long long)__float_as_uint(sg) << 21)
                                   | (unsigned long long)(0x1FFFFFu - idx);
            }
        }
    }

    // ---- elect last-done block of this batch to sort + decode --------------
    __threadfence();
    __syncthreads();
    if (tid == 0) s_od = (int)atomicAdd(&g_done[b], 1u);
    __syncthreads();
    if (s_od != GSPL - 1) return;
    __threadfence();

    unsigned cnt = g_count[b]; if (cnt > CAP) cnt = CAP;
    unsigned n2 = 256;                       // smallest pow2 >= cnt (min 256)
    while (n2 < cnt) n2 <<= 1;

    for (unsigned i = (unsigned)tid; i < n2; i += 256)
        sel[i] = (i < cnt) ? g_cand[b][i] : 0ull;
    __syncthreads();

    for (unsigned k = 2; k <= n2; k <<= 1)
        for (unsigned j = k >> 1; j > 0; j >>= 1) {
            for (unsigned i = (unsigned)tid; i < n2; i += 256) {
                unsigned ixj = i ^ j;
                if (ixj > i) {
                    unsigned long long a = sel[i], q = sel[ixj];
                    bool desc = ((i & k) == 0);
                    if (desc ? (a < q) : (a > q)) { sel[i] = q; sel[ixj] = a; }
                }
            }
            __syncthreads();
        }

    if (tid < KTOP) {
        unsigned long long key = sel[tid];
        float score = 0.0f; unsigned idx = 0u;
        if ((unsigned)tid < cnt) {
            score = __uint_as_float((unsigned)(key >> 21));
            idx   = 0x1FFFFFu - (unsigned)(key & 0x1FFFFFull);
        }
        unsigned cl = idx % CC;
        unsigned sp = idx / CC;
        unsigned xs = sp % WW;
        unsigned ys = sp / WW;
        const float* wh = det + (((size_t)b * HH + ys) * WW + xs) * CHN + CC;
        float w0 = wh[0], w1 = wh[1], w2 = wh[2], w3 = wh[3];
        float fy = (float)ys, fx = (float)xs;
        float* o = out + ((size_t)b * KTOP + tid) * 6;
        o[0] = (fy - w0) * 0.0078125f;
        o[1] = (fx - w1) * 0.0078125f;
        o[2] = (fy + w2) * 0.0078125f;
        o[3] = (fx + w3) * 0.0078125f;
        o[4] = (float)cl;
        o[5] = score;
    }

    // reset per-batch state for next graph replay (all readers are done:
    // every block of this batch read g_seg before incrementing g_done)
    __syncthreads();
    if (tid < 240) {
        ((unsigned*)g_seg[b])[tid] = 0u;
        ((unsigned*)g_seg[b])[tid + 240] = 0u;
    }
    if (tid == 0) { g_count[b] = 0u; g_done[b] = 0u; }
}

extern "C" void kernel_launch(void* const* d_in, const int* in_sizes, int n_in,
                              void* d_out, int out_size) {
    const float* det = (const float*)d_in[0];
    float* out = (float*)d_out;
    (void)in_sizes; (void)n_in; (void)out_size;

    pre_kernel<<<dim3(16, NB), 320>>>(det);
    gstopk_kernel<<<dim3(GSPL, NB), 256>>>(det, out);
}

// round 17
// speedup vs baseline: 1.5057x; 1.5057x over previous
#include <cuda_runtime.h>
#include <math.h>

#define NB    32
#define HH    128
#define WW    128
#define CC    80
#define CHN   84
#define KTOP  100
#define SORTN 2048
#define FQCAP 3072
#define Q2CAP 3072
#define NITEM (HH * 16 * 20)       /* 40960 scratch items per batch */

__device__ unsigned g_seg[NB][6][80];          /* zero-init = ord-map bottom */
__device__ float    g_scr[NB][HH][16][20];     /* max over 8x x 4ch cells   */

__device__ __forceinline__ unsigned ordmap(float x) {
    unsigned u = __float_as_uint(x);
    return (u & 0x80000000u) ? ~u : (u | 0x80000000u);
}
__device__ __forceinline__ float ordunmap(unsigned u) {
    return __uint_as_float((u & 0x80000000u) ? (u ^ 0x80000000u) : ~u);
}
__device__ __forceinline__ void upd4(float4& a, float4 v) {
    a.x = fmaxf(a.x, v.x); a.y = fmaxf(a.y, v.y);
    a.z = fmaxf(a.z, v.z); a.w = fmaxf(a.w, v.w);
}

// ===== Kernel 1: segment maxima (certification inputs) + coarse max map =====
// Lean streaming body (R13-proven). Thread = (row, half, 4ch-group).
// Per half: seg m0={x0}, m1=[1..62], m2={x63}; also per-(8x,4ch) cell max.
__global__ void __launch_bounds__(320, 3) pre_kernel(const float* __restrict__ det) {
    __shared__ unsigned sm_max[6][80];

    const int t    = threadIdx.x;
    const int b    = blockIdx.y;
    const int row  = blockIdx.x * 8 + t / 40;       // 16 strips of 8 rows
    const int half = (t / 20) & 1;
    const int cgi  = t % 20;
    const int cg   = cgi * 4;

    for (int i = t; i < 480; i += 320) ((unsigned*)sm_max)[i] = 0u;
    __syncthreads();

    const float NEGINF = __int_as_float(0xff800000);
    const float* rp = det + ((size_t)(b * HH + row) * WW + half * 64) * CHN + cg;

    float4 m0, m2;
    float4 m1 = make_float4(NEGINF, NEGINF, NEGINF, NEGINF);
    #pragma unroll
    for (int g = 0; g < 8; g++) {
        float4 a = make_float4(NEGINF, NEGINF, NEGINF, NEGINF);
        #pragma unroll
        for (int xx = 0; xx < 8; xx++) {
            float4 v = *(const float4*)(rp + (g * 8 + xx) * CHN);
            upd4(a, v);
            if (g == 0 && xx == 0)      m0 = v;
            else if (g == 7 && xx == 7) m2 = v;
            else                        upd4(m1, v);
        }
        g_scr[b][row][half * 8 + g][cgi] =
            fmaxf(fmaxf(a.x, a.y), fmaxf(a.z, a.w));
    }

    const int sb = half * 3;
    atomicMax(&sm_max[sb + 0][cg + 0], ordmap(m0.x));
    atomicMax(&sm_max[sb + 0][cg + 1], ordmap(m0.y));
    atomicMax(&sm_max[sb + 0][cg + 2], ordmap(m0.z));
    atomicMax(&sm_max[sb + 0][cg + 3], ordmap(m0.w));
    atomicMax(&sm_max[sb + 1][cg + 0], ordmap(m1.x));
    atomicMax(&sm_max[sb + 1][cg + 1], ordmap(m1.y));
    atomicMax(&sm_max[sb + 1][cg + 2], ordmap(m1.z));
    atomicMax(&sm_max[sb + 1][cg + 3], ordmap(m1.w));
    atomicMax(&sm_max[sb + 2][cg + 0], ordmap(m2.x));
    atomicMax(&sm_max[sb + 2][cg + 1], ordmap(m2.y));
    atomicMax(&sm_max[sb + 2][cg + 2], ordmap(m2.z));
    atomicMax(&sm_max[sb + 2][cg + 3], ordmap(m2.w));
    __syncthreads();

    for (int i = t; i < 480; i += 320)
        atomicMax(&((unsigned*)g_seg[b])[i], ((unsigned*)sm_max)[i]);
}

// ===== Kernel 2: certify + phased scan/filter/check + sort + decode =========
// One block per batch, 1024 threads. All candidate state stays in smem.
__global__ void __launch_bounds__(1024) topk_kernel(const float* __restrict__ det,
                                                    float* __restrict__ out) {
    const int b   = blockIdx.x;
    const int tid = threadIdx.x;
    __shared__ unsigned long long sel[SORTN];   // 16KB
    __shared__ unsigned fq[FQCAP];              // 12KB fired coarse items
    __shared__ unsigned q2[Q2CAP];              // 12KB cells needing window
    __shared__ unsigned s_vals[256];
    __shared__ float sh_T, sh_Tg;
    __shared__ int s_nf, s_n2, s_n;

    // ---- certification: per (half, channel) interior==region => true peak --
    unsigned val = 0u;
    if (tid < 160) {
        int h = tid / 80, ch = tid % 80;
        const unsigned* R = &g_seg[b][0][ch];
        unsigned R0 = R[0], R1 = R[80], R2 = R[160],
                 R3 = R[240], R4 = R[320], R5 = R[400];
        unsigned iu = h == 0 ? max(R1, R2) : max(R3, R4);
        unsigned ru = h == 0 ? max(iu, max(R0, R3)) : max(iu, max(R2, R5));
        if (iu == ru) val = iu;
    }
    if (tid < 256) s_vals[tid] = val;
    if (tid == 0) { s_nf = 0; s_n2 = 0; s_n = 0; }
    __syncthreads();
    for (unsigned k = 2; k <= 256; k <<= 1)
        for (unsigned j = k >> 1; j > 0; j >>= 1) {
            if (tid < 256) {
                unsigned i = (unsigned)tid, ixj = i ^ j;
                if (ixj > i) {
                    unsigned a = s_vals[i], q = s_vals[ixj];
                    bool desc = ((i & k) == 0);
                    if (desc ? (a < q) : (a > q)) { s_vals[i] = q; s_vals[ixj] = a; }
                }
            }
            __syncthreads();
        }
    if (tid == 0) {
        unsigned Tm = s_vals[99];
        float T, Tg;
        if (Tm == 0u) { T = -1e30f; Tg = -1e30f; }
        else {
            T = ordunmap(Tm);
            float sT = 1.0f / (1.0f + expf(-T));
            float a  = sT - 1e-4f;
            Tg = (a <= 0.0f) ? -1e30f : (logf(a / (1.0f - a)) - 1e-3f);
        }
        sh_T = T; sh_Tg = Tg;
    }
    __syncthreads();
    const float Tval = sh_T, Tg = sh_Tg;

    // ---- scan coarse max map (float4, high MLP) ----------------------------
    const float4* scr4 = (const float4*)&g_scr[b][0][0][0];
    #pragma unroll
    for (int u = 0; u < NITEM / 4096; u++) {        // 10 iters
        int i4 = tid + u * 1024;
        float4 v = scr4[i4];
        unsigned bi = (unsigned)i4 * 4u;
        if (v.x >= Tg) { int p = atomicAdd(&s_nf, 1); if (p < FQCAP) fq[p] = bi; }
        if (v.y >= Tg) { int p = atomicAdd(&s_nf, 1); if (p < FQCAP) fq[p] = bi + 1; }
        if (v.z >= Tg) { int p = atomicAdd(&s_nf, 1); if (p < FQCAP) fq[p] = bi + 2; }
        if (v.w >= Tg) { int p = atomicAdd(&s_nf, 1); if (p < FQCAP) fq[p] = bi + 3; }
    }
    __syncthreads();

    const float* base = det + (size_t)b * HH * WW * CHN;
    const bool fbA = (s_nf > FQCAP);                 // degenerate fallback
    const int ncell = (fbA ? NITEM : s_nf) * 32;

    // ---- phase A: one thread per center cell; queue cells with ctr >= Tg ---
    for (int c = tid; c < ncell; c += 1024) {
        unsigned item = fbA ? (unsigned)(c >> 5) : fq[c >> 5];
        int sub = c & 31;
        int cgi = (int)(item % 20u);
        int rx  = (int)(item / 20u);
        int x   = (rx & 15) * 8 + (sub >> 2);
        int r   = rx >> 4;
        int ch  = cgi * 4 + (sub & 3);
        float ctr = base[((size_t)r * WW + x) * CHN + ch];
        if (ctr >= Tg) {
            int p = atomicAdd(&s_n2, 1);
            if (p < Q2CAP)
                q2[p] = ((unsigned)r * WW + (unsigned)x) * CC + (unsigned)ch;
        }
    }
    __syncthreads();

    const bool fbB = (s_n2 > Q2CAP);
    const int tot = fbB ? ncell : s_n2;

    // ---- phase B: full 3x3 window check per queued cell --------------------
    for (int q = tid; q < tot; q += 1024) {
        unsigned idx;
        if (fbB) {                                   // recompute like phase A
            int c = q;
            unsigned item = fbA ? (unsigned)(c >> 5) : fq[c >> 5];
            int sub = c & 31;
            int cgi = (int)(item % 20u);
            int rx  = (int)(item / 20u);
            int x   = (rx & 15) * 8 + (sub >> 2);
            int r   = rx >> 4;
            int ch  = cgi * 4 + (sub & 3);
            idx = ((unsigned)r * WW + (unsigned)x) * CC + (unsigned)ch;
        } else {
            idx = q2[q];
        }
        int ch = (int)(idx % CC);
        int sp = (int)(idx / CC);
        int x  = sp % WW, r = sp / WW;

        float ctr = base[(size_t)sp * CHN + ch];     // L1-hot from phase A
        if (ctr < Tg) continue;
        float mm = ctr;
        #pragma unroll
        for (int dy = -1; dy <= 1; dy++) {
            int ry = min(HH - 1, max(0, r + dy));
            #pragma unroll
            for (int dx = -1; dx <= 1; dx++) {
                int rx2 = min(WW - 1, max(0, x + dx));
                mm = fmaxf(mm, base[((size_t)ry * WW + rx2) * CHN + ch]);
            }
        }
        float d = mm - ctr;
        bool cand = false;
        if (mm >= Tval) {
            if (d < 3.6e-4f) cand = true;            // sig-diff <= d/4 < 1e-4
            else if (d < 0.0421f ||
                     fmaxf(fabsf(ctr), fabsf(mm)) >= 6.0f) {
                float s  = 1.0f / (1.0f + expf(-ctr));
                float sm = 1.0f / (1.0f + expf(-mm));
                cand = fabsf(s - sm) < 1e-4f;
            }
        }
        if (cand) {
            float sg = 1.0f / (1.0f + expf(-mm));
            int p = atomicAdd(&s_n, 1);
            if (p < SORTN)
                sel[p] = ((unsigned long long)__float_as_uint(sg) << 21)
                       | (unsigned long long)(0x1FFFFFu - idx);
        }
    }
    __syncthreads();

    // ---- sort (dynamic size) + decode --------------------------------------
    int n = s_n; if (n > SORTN) n = SORTN;
    unsigned n2s = 256;
    while (n2s < (unsigned)n) n2s <<= 1;
    for (unsigned i = (unsigned)tid; i < n2s; i += 1024)
        if (i >= (unsigned)n) sel[i] = 0ull;
    __syncthreads();

    for (unsigned k = 2; k <= n2s; k <<= 1)
        for (unsigned j = k >> 1; j > 0; j >>= 1) {
            for (unsigned i = (unsigned)tid; i < n2s; i += 1024) {
                unsigned ixj = i ^ j;
                if (ixj > i) {
                    unsigned long long a = sel[i], q = sel[ixj];
                    bool desc = ((i & k) == 0);
                    if (desc ? (a < q) : (a > q)) { sel[i] = q; sel[ixj] = a; }
                }
            }
            __syncthreads();
        }

    if (tid < KTOP) {
        unsigned long long key = sel[tid];
        float score = 0.0f; unsigned idx = 0u;
        if (tid < n) {
            score = __uint_as_float((unsigned)(key >> 21));
            idx   = 0x1FFFFFu - (unsigned)(key & 0x1FFFFFull);
        }
        unsigned cl = idx % CC;
        unsigned sp = idx / CC;
        unsigned xs = sp % WW;
        unsigned ys = sp / WW;
        const float* wh = det + (((size_t)b * HH + ys) * WW + xs) * CHN + CC;
        float w0 = wh[0], w1 = wh[1], w2 = wh[2], w3 = wh[3];
        float fy = (float)ys, fx = (float)xs;
        float* o = out + ((size_t)b * KTOP + tid) * 6;
        o[0] = (fy - w0) * 0.0078125f;
        o[1] = (fx - w1) * 0.0078125f;
        o[2] = (fy + w2) * 0.0078125f;
        o[3] = (fx + w3) * 0.0078125f;
        o[4] = (float)cl;
        o[5] = score;
    }

    // reset per-batch state for next graph replay
    __syncthreads();
    if (tid < 480) ((unsigned*)g_seg[b])[tid] = 0u;
}

extern "C" void kernel_launch(void* const* d_in, const int* in_sizes, int n_in,
                              void* d_out, int out_size) {
    const float* det = (const float*)d_in[0];
    float* out = (float*)d_out;
    (void)in_sizes; (void)n_in; (void)out_size;

    pre_kernel<<<dim3(16, NB), 320>>>(det);
    topk_kernel<<<NB, 1024>>>(det, out);
}